// round 16
// baseline (speedup 1.0000x reference)
#include <cuda_runtime.h>
#include <cuda_fp16.h>
#include <cstdint>

#define M_DIM 4096
#define K_DIM 4096
#define N_DIM 4096
#define NV4_N 2048
#define FP8_N 1024

#define BM 128
#define BN 128
#define BK 64
#define STAGES 3
#define NITER (K_DIM / BK)     // 64
#define NTHREADS 256

#define TILES_TOTAL 1024
#define TILES_FULL  888        // exactly 3 waves of 296 slots (148 SM x 2 CTA)
#define TAIL        (TILES_TOTAL - TILES_FULL)   // 136 tiles, split-K in 2 halves
#define TAIL_ELEMS  (TAIL * BM * BN)             // 2228224 floats

// ---- scratch (device globals: allowed) ----
__device__ __half g_Wh[(size_t)N_DIM * K_DIM];   // 32 MB dequantized+permuted W (fp16)
__device__ __half g_Xh[(size_t)M_DIM * K_DIM];   // 32 MB fp16 X
__device__ float  g_part[(size_t)TAIL_ELEMS];    // 8.9 MB k-hi partial sums

__constant__ float c_code[16] = {0.f, 0.5f, 1.f, 1.5f, 2.f, 3.f, 4.f, 6.f,
                                 -0.f, -0.5f, -1.f, -1.5f, -2.f, -3.f, -4.f, -6.f};

// ================= helpers =================
__device__ __forceinline__ uint32_t smem_u32(const void* p) {
    uint32_t a;
    asm("{ .reg .u64 t; cvta.to.shared.u64 t, %1; cvt.u32.u64 %0, t; }" : "=r"(a) : "l"(p));
    return a;
}
#define CP_ASYNC16(dst, src) \
    asm volatile("cp.async.cg.shared.global [%0], [%1], 16;" :: "r"(dst), "l"(src) : "memory")
#define CP_COMMIT() asm volatile("cp.async.commit_group;" ::: "memory")
#define CP_WAIT1()  asm volatile("cp.async.wait_group 1;" ::: "memory")
#define CP_WAIT0()  asm volatile("cp.async.wait_group 0;" ::: "memory")

#define LDSM_X4(r0, r1, r2, r3, addr) \
    asm volatile("ldmatrix.sync.aligned.m8n8.x4.shared.b16 {%0,%1,%2,%3}, [%4];" \
                 : "=r"(r0), "=r"(r1), "=r"(r2), "=r"(r3) : "r"(addr))

#define MMA16816(c, a, b) \
    asm volatile("mma.sync.aligned.m16n8k16.row.col.f32.f16.f16.f32 " \
                 "{%0,%1,%2,%3}, {%4,%5,%6,%7}, {%8,%9}, {%0,%1,%2,%3};" \
                 : "+f"((c)[0]), "+f"((c)[1]), "+f"((c)[2]), "+f"((c)[3]) \
                 : "r"((a)[0]), "r"((a)[1]), "r"((a)[2]), "r"((a)[3]), \
                   "r"((b)[0]), "r"((b)[1]))

__device__ __forceinline__ void stcs_f2(float* p, float2 v) {
    asm volatile("st.global.cs.v2.f32 [%0], {%1, %2};" :: "l"(p), "f"(v.x), "f"(v.y) : "memory");
}

#define SW128(off) ((off) ^ (((off) >> 3) & 0x70))

// SMEM per CTA: A stages 16KB each (128 rows x 128B), B stages 16KB each
#define SM_A(s)  ((s) * 16384)
#define SM_B(s)  (49152 + (s) * 16384)
#define SMEM_TOTAL 98304   // 96KB -> 2 CTAs/SM

// ================= prep (X convert + W dequant, perm dtype probe inlined) =================
// dtype probe (validated R12-R15): int32 data misread as int64 gives p64[i] = lo + hi*2^32.
// A permutation of [0,4096) has exactly one 0, so int32 elements at positions 1 and 3
// cannot both be 0 -> at least one of p64[0], p64[1] overflows. Genuine int64: both valid.
__device__ __forceinline__ int perm_at(const void* perm_raw, int j) {
    const long long* p64 = (const long long*)perm_raw;
    const bool is64 = ((unsigned long long)p64[0] < (unsigned long long)N_DIM) &&
                      ((unsigned long long)p64[1] < (unsigned long long)N_DIM);
    return is64 ? (int)p64[j] : ((const int*)perm_raw)[j];
}

#define XCONV_BLOCKS 2048
__global__ void prep_kernel(const float* __restrict__ X,
                            const int* __restrict__ nvfp4_idx,
                            const float* __restrict__ nvfp4_scales,
                            const float* __restrict__ gscale_p,
                            const float* __restrict__ w_fp8,
                            const float* __restrict__ fp8_scale_p,
                            const float* __restrict__ w_fp16,
                            const void* __restrict__ perm_raw)
{
    const int tid = threadIdx.x;
    if (blockIdx.x < XCONV_BLOCKS) {
        size_t base = ((size_t)blockIdx.x * 256 + tid) * 8;
        const size_t stride = (size_t)XCONV_BLOCKS * 256 * 8;
        #pragma unroll
        for (int r = 0; r < 4; r++, base += stride) {
            float4 a = *(const float4*)(X + base);
            float4 b = *(const float4*)(X + base + 4);
            __half2 h[4];
            h[0] = __floats2half2_rn(a.x, a.y);
            h[1] = __floats2half2_rn(a.z, a.w);
            h[2] = __floats2half2_rn(b.x, b.y);
            h[3] = __floats2half2_rn(b.z, b.w);
            *(uint4*)(g_Xh + base) = *(uint4*)h;
        }
        return;
    }
    const int j = blockIdx.x - XCONV_BLOCKS;
    const int g = perm_at(perm_raw, j);
    __half* __restrict__ dst = &g_Wh[(size_t)j * K_DIM];

    if (g < NV4_N) {
        // smem LUT (R15 win): divergent indexed loads serialize on the broadcast-only
        // constant port; LDS handles divergent words at low conflict degree.
        __shared__ float lut[16];
        if (tid < 16) lut[tid] = c_code[tid];
        __syncthreads();

        const float gs = gscale_p[0];
        const int* __restrict__ idx = nvfp4_idx + (size_t)g * K_DIM;
        const float* __restrict__ sc = nvfp4_scales + (size_t)g * (K_DIM / 16);
        const int k = tid * 16;   // 256 threads x 16 = 4096 = K
        const float s = sc[k >> 4] * gs;
        #pragma unroll
        for (int c = 0; c < 16; c += 8) {
            int4 i0 = *(const int4*)&idx[k + c];
            int4 i1 = *(const int4*)&idx[k + c + 4];
            __half2 h[4];
            h[0] = __floats2half2_rn(lut[i0.x & 15] * s, lut[i0.y & 15] * s);
            h[1] = __floats2half2_rn(lut[i0.z & 15] * s, lut[i0.w & 15] * s);
            h[2] = __floats2half2_rn(lut[i1.x & 15] * s, lut[i1.y & 15] * s);
            h[3] = __floats2half2_rn(lut[i1.z & 15] * s, lut[i1.w & 15] * s);
            *(uint4*)&dst[k + c] = *(uint4*)h;
        }
    } else {
        const bool is8 = (g < NV4_N + FP8_N);
        const float fs = is8 ? fp8_scale_p[0] : 1.f;
        const float* __restrict__ w = is8 ? (w_fp8 + (size_t)(g - NV4_N) * K_DIM)
                                          : (w_fp16 + (size_t)(g - NV4_N - FP8_N) * K_DIM);
        for (int k = tid * 8; k < K_DIM; k += 256 * 8) {
            float4 a = *(const float4*)&w[k];
            float4 b = *(const float4*)&w[k + 4];
            __half2 h[4];
            h[0] = __floats2half2_rn(a.x * fs, a.y * fs);
            h[1] = __floats2half2_rn(a.z * fs, a.w * fs);
            h[2] = __floats2half2_rn(b.x * fs, b.y * fs);
            h[3] = __floats2half2_rn(b.z * fs, b.w * fs);
            *(uint4*)&dst[k] = *(uint4*)h;
        }
    }
}

// ===== HMMA GEMM (R13 core; 888 full tiles + 272 split-K tail halves) =====
__device__ __forceinline__ void load_stage(uint32_t smem_base, int s, int it, int m0, int n0)
{
    const int tid = threadIdx.x;
    const int k0 = it * BK;
    const uint32_t a_base = smem_base + SM_A(s);
    const uint32_t b_base = smem_base + SM_B(s);
    #pragma unroll
    for (int i = 0; i < 4; i++) {
        int gr = tid + i * NTHREADS;
        int row = gr >> 3, c16 = gr & 7;
        const __half* src = g_Xh + (size_t)(m0 + row) * K_DIM + k0 + c16 * 8;
        uint32_t off = row * 128 + c16 * 16;
        CP_ASYNC16(a_base + SW128(off), src);
    }
    #pragma unroll
    for (int i = 0; i < 4; i++) {
        int gr = tid + i * NTHREADS;
        int row = gr >> 3, c16 = gr & 7;
        const __half* src = g_Wh + (size_t)(n0 + row) * K_DIM + k0 + c16 * 8;
        uint32_t off = row * 128 + c16 * 16;
        CP_ASYNC16(b_base + SW128(off), src);
    }
}

__global__ __launch_bounds__(NTHREADS, 2)
void gemm_hmma_kernel(const float* __restrict__ bias, float* __restrict__ out)
{
    extern __shared__ char smem[];
    const uint32_t smem_base = smem_u32(smem);
    const int tid  = threadIdx.x;
    const int wid  = tid >> 5, lane = tid & 31;
    const int wm   = wid & 3;            // 4 warps along M (32 rows each)
    const int wn   = wid >> 2;           // 2 warps along N (64 cols each)

    // tile assignment: full tiles first (3 exact waves), split-K tail halves last
    const int bid = blockIdx.x;
    int t, it0, it1;
    bool to_out;
    if (bid < TILES_FULL) {
        t = bid; it0 = 0; it1 = NITER; to_out = true;
    } else {
        const int idx = bid - TILES_FULL;
        t = TILES_FULL + (idx % TAIL);
        const int half = idx / TAIL;     // 0 = k-lo (writes out+bias), 1 = k-hi (writes g_part)
        it0 = half * (NITER / 2); it1 = it0 + NITER / 2;
        to_out = (half == 0);
    }
    const int m0 = (t & 31) * BM;        // m fastest
    const int n0 = (t >> 5) * BN;

    float acc[2][8][4] = {};             // 64 regs

    const int a_row_b = (lane & 15);
    const int a_kh  = (lane >> 4) * 8;
    const int b_row_b = (lane >> 4) * 8 + (lane & 7);
    const int b_kh  = ((lane >> 3) & 1) * 8;

    #pragma unroll
    for (int s = 0; s < STAGES - 1; s++) {
        load_stage(smem_base, (it0 + s) % STAGES, it0 + s, m0, n0); CP_COMMIT();
    }

    for (int it = it0; it < it1; it++) {
        const int s = it % STAGES;
        if (it == it1 - 1) CP_WAIT0(); else CP_WAIT1();
        __syncthreads();

        const int nxt = it + STAGES - 1;
        if (nxt < it1) { load_stage(smem_base, nxt % STAGES, nxt, m0, n0); CP_COMMIT(); }

        const uint32_t a_base = smem_base + SM_A(s);
        const uint32_t b_base = smem_base + SM_B(s);

        #pragma unroll
        for (int kk = 0; kk < 4; kk++) {          // 4 x k16 per BK=64
            const int k0 = kk * 16;
            uint32_t af[2][4];
            #pragma unroll
            for (int mt = 0; mt < 2; mt++) {
                uint32_t off = (wm * 32 + mt * 16 + a_row_b) * 128 + (k0 + a_kh) * 2;
                LDSM_X4(af[mt][0], af[mt][1], af[mt][2], af[mt][3],
                        a_base + SW128(off));
            }
            uint32_t bf[8][2];
            #pragma unroll
            for (int p = 0; p < 4; p++) {
                uint32_t off = (wn * 64 + p * 16 + b_row_b) * 128 + (k0 + b_kh) * 2;
                LDSM_X4(bf[2 * p][0], bf[2 * p][1], bf[2 * p + 1][0], bf[2 * p + 1][1],
                        b_base + SW128(off));
            }
            #pragma unroll
            for (int mt = 0; mt < 2; mt++)
                #pragma unroll
                for (int nt = 0; nt < 8; nt++)
                    MMA16816(acc[mt][nt], af[mt], bf[nt]);
        }
    }

    // epilogue
    const int er = lane >> 2;
    const int ec = (lane & 3) * 2;
    if (to_out) {
        #pragma unroll
        for (int nt = 0; nt < 8; nt++) {
            const int n = n0 + wn * 64 + nt * 8 + ec;
            const float2 bv = *(const float2*)(bias + n);
            #pragma unroll
            for (int mt = 0; mt < 2; mt++) {
                const int m = m0 + wm * 32 + mt * 16 + er;
                float2 v0 = { acc[mt][nt][0] + bv.x, acc[mt][nt][1] + bv.y };
                float2 v1 = { acc[mt][nt][2] + bv.x, acc[mt][nt][3] + bv.y };
                stcs_f2(out + (size_t)m * N_DIM + n, v0);
                stcs_f2(out + (size_t)(m + 8) * N_DIM + n, v1);
            }
        }
    } else {
        float* pb = g_part + (size_t)(t - TILES_FULL) * (BM * BN);
        #pragma unroll
        for (int nt = 0; nt < 8; nt++) {
            const int nl = wn * 64 + nt * 8 + ec;
            #pragma unroll
            for (int mt = 0; mt < 2; mt++) {
                const int ml = wm * 32 + mt * 16 + er;
                float2 v0 = { acc[mt][nt][0], acc[mt][nt][1] };
                float2 v1 = { acc[mt][nt][2], acc[mt][nt][3] };
                stcs_f2(pb + (size_t)ml * BN + nl, v0);
                stcs_f2(pb + (size_t)(ml + 8) * BN + nl, v1);
            }
        }
    }
}

// add k-hi partials into out for the 136 tail tiles
__global__ void reduce_kernel(float* __restrict__ out)
{
    const size_t flat = ((size_t)blockIdx.x * 256 + threadIdx.x) * 4;
    if (flat >= TAIL_ELEMS) return;
    const int tile  = (int)(flat >> 14);          // /16384
    const int local = (int)(flat & 16383);
    const int ml = local >> 7, nl = local & 127;
    const int t  = TILES_FULL + tile;
    const int m0 = (t & 31) * BM;
    const int n0 = (t >> 5) * BN;
    float4 p = *(const float4*)&g_part[flat];
    float* o = out + (size_t)(m0 + ml) * N_DIM + n0 + nl;
    float4 v = *(const float4*)o;
    v.x += p.x; v.y += p.y; v.z += p.z; v.w += p.w;
    *(float4*)o = v;
}

// ================= launch =================
extern "C" void kernel_launch(void* const* d_in, const int* in_sizes, int n_in,
                              void* d_out, int out_size)
{
    const float* x            = (const float*)d_in[0];
    const int*   nvfp4_idx    = (const int*)d_in[1];
    const float* nvfp4_scales = (const float*)d_in[2];
    const float* nvfp4_gscale = (const float*)d_in[3];
    const float* w_fp8        = (const float*)d_in[4];
    const float* fp8_scale    = (const float*)d_in[5];
    const float* w_fp16       = (const float*)d_in[6];
    const float* bias         = (const float*)d_in[7];
    const void*  inv_perm     = (const void*)d_in[8];
    float*       out          = (float*)d_out;

    cudaFuncSetAttribute(gemm_hmma_kernel, cudaFuncAttributeMaxDynamicSharedMemorySize, SMEM_TOTAL);

    prep_kernel<<<XCONV_BLOCKS + N_DIM, 256>>>(x, nvfp4_idx, nvfp4_scales, nvfp4_gscale,
                                               w_fp8, fp8_scale, w_fp16, inv_perm);

    gemm_hmma_kernel<<<TILES_FULL + 2 * TAIL, NTHREADS, SMEM_TOTAL>>>(bias, out);

    reduce_kernel<<<(TAIL_ELEMS / 4 + 255) / 256, 256>>>(out);
}

// round 17
// speedup vs baseline: 1.1345x; 1.1345x over previous
#include <cuda_runtime.h>
#include <cuda_fp16.h>
#include <cstdint>

#define M_DIM 4096
#define K_DIM 4096
#define N_DIM 4096
#define NV4_N 2048
#define FP8_N 1024

#define BM 128
#define BN 128
#define BK 64
#define STAGES 3
#define NITER (K_DIM / BK)     // 64
#define NTHREADS 256

// ---- scratch (device globals: allowed) ----
__device__ __half g_Wh[(size_t)N_DIM * K_DIM];   // 32 MB dequantized+permuted W (fp16)
__device__ __half g_Xh[(size_t)M_DIM * K_DIM];   // 32 MB fp16 X

__constant__ float c_code[16] = {0.f, 0.5f, 1.f, 1.5f, 2.f, 3.f, 4.f, 6.f,
                                 -0.f, -0.5f, -1.f, -1.5f, -2.f, -3.f, -4.f, -6.f};

// ================= helpers =================
__device__ __forceinline__ uint32_t smem_u32(const void* p) {
    uint32_t a;
    asm("{ .reg .u64 t; cvta.to.shared.u64 t, %1; cvt.u32.u64 %0, t; }" : "=r"(a) : "l"(p));
    return a;
}
#define CP_ASYNC16(dst, src) \
    asm volatile("cp.async.cg.shared.global [%0], [%1], 16;" :: "r"(dst), "l"(src) : "memory")
#define CP_COMMIT() asm volatile("cp.async.commit_group;" ::: "memory")
#define CP_WAIT1()  asm volatile("cp.async.wait_group 1;" ::: "memory")
#define CP_WAIT0()  asm volatile("cp.async.wait_group 0;" ::: "memory")

#define LDSM_X4(r0, r1, r2, r3, addr) \
    asm volatile("ldmatrix.sync.aligned.m8n8.x4.shared.b16 {%0,%1,%2,%3}, [%4];" \
                 : "=r"(r0), "=r"(r1), "=r"(r2), "=r"(r3) : "r"(addr))

#define MMA16816(c, a, b) \
    asm volatile("mma.sync.aligned.m16n8k16.row.col.f32.f16.f16.f32 " \
                 "{%0,%1,%2,%3}, {%4,%5,%6,%7}, {%8,%9}, {%0,%1,%2,%3};" \
                 : "+f"((c)[0]), "+f"((c)[1]), "+f"((c)[2]), "+f"((c)[3]) \
                 : "r"((a)[0]), "r"((a)[1]), "r"((a)[2]), "r"((a)[3]), \
                   "r"((b)[0]), "r"((b)[1]))

// streaming store (output is write-once; keep L2 for operands)
__device__ __forceinline__ void stcs_f2(float* p, float2 v) {
    asm volatile("st.global.cs.v2.f32 [%0], {%1, %2};" :: "l"(p), "f"(v.x), "f"(v.y) : "memory");
}

#define SW128(off) ((off) ^ (((off) >> 3) & 0x70))

// SMEM per CTA: A stages 16KB each (128 rows x 128B), B stages 16KB each
#define SM_A(s)  ((s) * 16384)
#define SM_B(s)  (49152 + (s) * 16384)
#define SMEM_TOTAL 98304   // 96KB -> 2 CTAs/SM

// ================= prep (X convert + W dequant, perm dtype probe inlined) =================
// dtype probe (validated R12-R16): int32 data misread as int64 gives p64[i] = lo + hi*2^32.
// A permutation of [0,4096) has exactly one 0, so int32 elements at positions 1 and 3
// cannot both be 0 -> at least one of p64[0], p64[1] overflows. Genuine int64: both valid.
__device__ __forceinline__ int perm_at(const void* perm_raw, int j) {
    const long long* p64 = (const long long*)perm_raw;
    const bool is64 = ((unsigned long long)p64[0] < (unsigned long long)N_DIM) &&
                      ((unsigned long long)p64[1] < (unsigned long long)N_DIM);
    return is64 ? (int)p64[j] : ((const int*)perm_raw)[j];
}

#define XCONV_BLOCKS 2048
__global__ void prep_kernel(const float* __restrict__ X,
                            const int* __restrict__ nvfp4_idx,
                            const float* __restrict__ nvfp4_scales,
                            const float* __restrict__ gscale_p,
                            const float* __restrict__ w_fp8,
                            const float* __restrict__ fp8_scale_p,
                            const float* __restrict__ w_fp16,
                            const void* __restrict__ perm_raw)
{
    const int tid = threadIdx.x;
    if (blockIdx.x < XCONV_BLOCKS) {
        size_t base = ((size_t)blockIdx.x * 256 + tid) * 8;
        const size_t stride = (size_t)XCONV_BLOCKS * 256 * 8;
        #pragma unroll
        for (int r = 0; r < 4; r++, base += stride) {
            float4 a = *(const float4*)(X + base);
            float4 b = *(const float4*)(X + base + 4);
            __half2 h[4];
            h[0] = __floats2half2_rn(a.x, a.y);
            h[1] = __floats2half2_rn(a.z, a.w);
            h[2] = __floats2half2_rn(b.x, b.y);
            h[3] = __floats2half2_rn(b.z, b.w);
            *(uint4*)(g_Xh + base) = *(uint4*)h;
        }
        return;
    }
    const int j = blockIdx.x - XCONV_BLOCKS;
    const int g = perm_at(perm_raw, j);
    __half* __restrict__ dst = &g_Wh[(size_t)j * K_DIM];

    if (g < NV4_N) {
        // smem LUT (R15 win): divergent indexed loads serialize on the broadcast-only
        // constant port; LDS handles divergent words at low conflict degree.
        __shared__ float lut[16];
        if (tid < 16) lut[tid] = c_code[tid];
        __syncthreads();

        const float gs = gscale_p[0];
        const int* __restrict__ idx = nvfp4_idx + (size_t)g * K_DIM;
        const float* __restrict__ sc = nvfp4_scales + (size_t)g * (K_DIM / 16);
        const int k = tid * 16;   // 256 threads x 16 = 4096 = K
        const float s = sc[k >> 4] * gs;
        #pragma unroll
        for (int c = 0; c < 16; c += 8) {
            int4 i0 = *(const int4*)&idx[k + c];
            int4 i1 = *(const int4*)&idx[k + c + 4];
            __half2 h[4];
            h[0] = __floats2half2_rn(lut[i0.x & 15] * s, lut[i0.y & 15] * s);
            h[1] = __floats2half2_rn(lut[i0.z & 15] * s, lut[i0.w & 15] * s);
            h[2] = __floats2half2_rn(lut[i1.x & 15] * s, lut[i1.y & 15] * s);
            h[3] = __floats2half2_rn(lut[i1.z & 15] * s, lut[i1.w & 15] * s);
            *(uint4*)&dst[k + c] = *(uint4*)h;
        }
    } else {
        const bool is8 = (g < NV4_N + FP8_N);
        const float fs = is8 ? fp8_scale_p[0] : 1.f;
        const float* __restrict__ w = is8 ? (w_fp8 + (size_t)(g - NV4_N) * K_DIM)
                                          : (w_fp16 + (size_t)(g - NV4_N - FP8_N) * K_DIM);
        for (int k = tid * 8; k < K_DIM; k += 256 * 8) {
            float4 a = *(const float4*)&w[k];
            float4 b = *(const float4*)&w[k + 4];
            __half2 h[4];
            h[0] = __floats2half2_rn(a.x * fs, a.y * fs);
            h[1] = __floats2half2_rn(a.z * fs, a.w * fs);
            h[2] = __floats2half2_rn(b.x * fs, b.y * fs);
            h[3] = __floats2half2_rn(b.z * fs, b.w * fs);
            *(uint4*)&dst[k] = *(uint4*)h;
        }
    }
}

// ===== HMMA GEMM (R15 optimum core: 128x128, 256 thr, 8 warps 4Mx2N, 2 CTAs/SM) =====
__device__ __forceinline__ void load_stage(uint32_t smem_base, int s, int it, int m0, int n0)
{
    const int tid = threadIdx.x;
    const int k0 = it * BK;
    const uint32_t a_base = smem_base + SM_A(s);
    const uint32_t b_base = smem_base + SM_B(s);
    #pragma unroll
    for (int i = 0; i < 4; i++) {
        int gr = tid + i * NTHREADS;
        int row = gr >> 3, c16 = gr & 7;
        const __half* src = g_Xh + (size_t)(m0 + row) * K_DIM + k0 + c16 * 8;
        uint32_t off = row * 128 + c16 * 16;
        CP_ASYNC16(a_base + SW128(off), src);
    }
    #pragma unroll
    for (int i = 0; i < 4; i++) {
        int gr = tid + i * NTHREADS;
        int row = gr >> 3, c16 = gr & 7;
        const __half* src = g_Wh + (size_t)(n0 + row) * K_DIM + k0 + c16 * 8;
        uint32_t off = row * 128 + c16 * 16;
        CP_ASYNC16(b_base + SW128(off), src);
    }
}

__global__ __launch_bounds__(NTHREADS, 2)
void gemm_hmma_kernel(const float* __restrict__ bias, float* __restrict__ out)
{
    extern __shared__ char smem[];
    const uint32_t smem_base = smem_u32(smem);
    const int tid  = threadIdx.x;
    const int wid  = tid >> 5, lane = tid & 31;
    const int wm   = wid & 3;            // 4 warps along M (32 rows each)
    const int wn   = wid >> 2;           // 2 warps along N (64 cols each)
    const int m0   = blockIdx.y * BM;
    const int n0   = blockIdx.x * BN;

    float acc[2][8][4] = {};             // 64 regs

    const int a_row_b = (lane & 15);
    const int a_kh  = (lane >> 4) * 8;
    const int b_row_b = (lane >> 4) * 8 + (lane & 7);
    const int b_kh  = ((lane >> 3) & 1) * 8;

    #pragma unroll
    for (int s = 0; s < STAGES - 1; s++) { load_stage(smem_base, s, s, m0, n0); CP_COMMIT(); }

    #pragma unroll 3
    for (int it = 0; it < NITER; it++) {
        const int s = it % STAGES;       // compile-time under unroll-3 (NITER % 3 != 0 handled by ptxas epilogue)
        if (it == NITER - 1) CP_WAIT0(); else CP_WAIT1();
        __syncthreads();

        const uint32_t a_base = smem_base + SM_A(s);
        const uint32_t b_base = smem_base + SM_B(s);

        // kk = 0: restart the tensor pipe FIRST (before spending issue slots on cp.async)
        uint32_t af[2][4];
        uint32_t bf[8][2];
        #pragma unroll
        for (int mt = 0; mt < 2; mt++) {
            uint32_t off = (wm * 32 + mt * 16 + a_row_b) * 128 + a_kh * 2;
            LDSM_X4(af[mt][0], af[mt][1], af[mt][2], af[mt][3], a_base + SW128(off));
        }
        #pragma unroll
        for (int p = 0; p < 4; p++) {
            uint32_t off = (wn * 64 + p * 16 + b_row_b) * 128 + b_kh * 2;
            LDSM_X4(bf[2 * p][0], bf[2 * p][1], bf[2 * p + 1][0], bf[2 * p + 1][1],
                    b_base + SW128(off));
        }
        #pragma unroll
        for (int mt = 0; mt < 2; mt++)
            #pragma unroll
            for (int nt = 0; nt < 8; nt++)
                MMA16816(acc[mt][nt], af[mt], bf[nt]);

        // now issue next stage's global loads (tensor pipe already busy)
        const int nxt = it + STAGES - 1;
        if (nxt < NITER) { load_stage(smem_base, nxt % STAGES, nxt, m0, n0); CP_COMMIT(); }

        // kk = 1..3
        #pragma unroll
        for (int kk = 1; kk < 4; kk++) {
            const int k0 = kk * 16;
            #pragma unroll
            for (int mt = 0; mt < 2; mt++) {
                uint32_t off = (wm * 32 + mt * 16 + a_row_b) * 128 + (k0 + a_kh) * 2;
                LDSM_X4(af[mt][0], af[mt][1], af[mt][2], af[mt][3], a_base + SW128(off));
            }
            #pragma unroll
            for (int p = 0; p < 4; p++) {
                uint32_t off = (wn * 64 + p * 16 + b_row_b) * 128 + (k0 + b_kh) * 2;
                LDSM_X4(bf[2 * p][0], bf[2 * p][1], bf[2 * p + 1][0], bf[2 * p + 1][1],
                        b_base + SW128(off));
            }
            #pragma unroll
            for (int mt = 0; mt < 2; mt++)
                #pragma unroll
                for (int nt = 0; nt < 8; nt++)
                    MMA16816(acc[mt][nt], af[mt], bf[nt]);
        }
    }

    // epilogue: streaming stores
    const int er = lane >> 2;
    const int ec = (lane & 3) * 2;
    #pragma unroll
    for (int nt = 0; nt < 8; nt++) {
        const int n = n0 + wn * 64 + nt * 8 + ec;
        const float2 bv = *(const float2*)(bias + n);
        #pragma unroll
        for (int mt = 0; mt < 2; mt++) {
            const int m = m0 + wm * 32 + mt * 16 + er;
            float2 v0 = { acc[mt][nt][0] + bv.x, acc[mt][nt][1] + bv.y };
            float2 v1 = { acc[mt][nt][2] + bv.x, acc[mt][nt][3] + bv.y };
            stcs_f2(out + (size_t)m * N_DIM + n, v0);
            stcs_f2(out + (size_t)(m + 8) * N_DIM + n, v1);
        }
    }
}

// ================= launch =================
extern "C" void kernel_launch(void* const* d_in, const int* in_sizes, int n_in,
                              void* d_out, int out_size)
{
    const float* x            = (const float*)d_in[0];
    const int*   nvfp4_idx    = (const int*)d_in[1];
    const float* nvfp4_scales = (const float*)d_in[2];
    const float* nvfp4_gscale = (const float*)d_in[3];
    const float* w_fp8        = (const float*)d_in[4];
    const float* fp8_scale    = (const float*)d_in[5];
    const float* w_fp16       = (const float*)d_in[6];
    const float* bias         = (const float*)d_in[7];
    const void*  inv_perm     = (const void*)d_in[8];
    float*       out          = (float*)d_out;

    cudaFuncSetAttribute(gemm_hmma_kernel, cudaFuncAttributeMaxDynamicSharedMemorySize, SMEM_TOTAL);

    prep_kernel<<<XCONV_BLOCKS + N_DIM, 256>>>(x, nvfp4_idx, nvfp4_scales, nvfp4_gscale,
                                               w_fp8, fp8_scale, w_fp16, inv_perm);

    dim3 grid(N_DIM / BN, M_DIM / BM);   // (32, 32)
    gemm_hmma_kernel<<<grid, NTHREADS, SMEM_TOTAL>>>(bias, out);
}